// round 2
// baseline (speedup 1.0000x reference)
#include <cuda_runtime.h>
#include <cstdint>

#define NN 100000
#define NE 1600000
#define DD 128

// ---------------- static device scratch (no allocations allowed) ----------------
__device__ float g_agg[(size_t)NN * DD];   // scatter-sum accumulator
__device__ float g_buf0[(size_t)NN * DD];  // layer-1 output
__device__ float g_buf1[(size_t)NN * DD];  // layer-2 output
__device__ float g_inv[NN];                // degree count, then 1/max(cnt,1)

// ---------------- utility kernels ----------------
__global__ void zero_agg_kernel() {
    size_t stride = (size_t)gridDim.x * blockDim.x;
    size_t n4 = (size_t)NN * DD / 4;
    float4 z = make_float4(0.f, 0.f, 0.f, 0.f);
    for (size_t v = (size_t)blockIdx.x * blockDim.x + threadIdx.x; v < n4; v += stride)
        reinterpret_cast<float4*>(g_agg)[v] = z;
}

__global__ void zero_inv_kernel() {
    int i = blockIdx.x * blockDim.x + threadIdx.x;
    if (i < NN) g_inv[i] = 0.f;
}

__global__ void count_kernel(const int* __restrict__ dst) {
    int stride = gridDim.x * blockDim.x;
    for (int e = blockIdx.x * blockDim.x + threadIdx.x; e < NE; e += stride)
        atomicAdd(&g_inv[dst[e]], 1.0f);
}

__global__ void invert_kernel() {
    int i = blockIdx.x * blockDim.x + threadIdx.x;
    if (i < NN) g_inv[i] = 1.0f / fmaxf(g_inv[i], 1.0f);
}

// ---------------- scatter: one warp per edge, coalesced scalar atomics --------
// hsel: 0 -> xin, 1 -> g_buf0, 2 -> g_buf1
__global__ void scatter_kernel(const float* __restrict__ xin,
                               const int* __restrict__ src,
                               const int* __restrict__ dst,
                               int hsel) {
    const float* __restrict__ x =
        (hsel == 0) ? xin : (hsel == 1) ? (const float*)g_buf0 : (const float*)g_buf1;
    int gw   = (blockIdx.x * blockDim.x + threadIdx.x) >> 5;
    int lane = threadIdx.x & 31;
    int nw   = (gridDim.x * blockDim.x) >> 5;
    for (int e = gw; e < NE; e += nw) {
        int s = __ldg(src + e);   // uniform within warp -> broadcast
        int d = __ldg(dst + e);
        const float* xp = x + (size_t)s * DD + lane;
        float*       ap = g_agg + (size_t)d * DD + lane;
        // per-instruction footprint: 32 consecutive floats = one 128B line
        float v0 = xp[0];
        float v1 = xp[32];
        float v2 = xp[64];
        float v3 = xp[96];
        atomicAdd(ap +  0, v0);
        atomicAdd(ap + 32, v1);
        atomicAdd(ap + 64, v2);
        atomicAdd(ap + 96, v3);
    }
}

// ---------------- fused SGEMM: out = (agg*inv)@Wl + h@Wr + bl + h (+ReLU) -------
// Block tile 128x128, K=256 (concat [agg*inv | h] x [Wl;Wr]), BK=16,
// 256 threads, 8x8 micro-tile per thread.
#define ASTRIDE 132

__global__ __launch_bounds__(256, 2)
void sage_gemm_kernel(const float* __restrict__ xin,
                      float* __restrict__ oout,
                      const float* __restrict__ Wl,
                      const float* __restrict__ Wr,
                      const float* __restrict__ bias,
                      int hsel, int osel, int do_relu) {
    const float* __restrict__ h =
        (hsel == 0) ? xin : (hsel == 1) ? (const float*)g_buf0 : (const float*)g_buf1;
    float* __restrict__ out =
        (osel == 0) ? (float*)g_buf0 : (osel == 1) ? (float*)g_buf1 : oout;

    __shared__ float As[16 * ASTRIDE];  // [k][row], padded
    __shared__ float Bs[16 * 128];      // [k][col]

    const int tid = threadIdx.x;
    const int tx = tid & 15;            // col group
    const int ty = tid >> 4;            // row group
    const int rowBase = blockIdx.x * 128;

    // Fixed per-thread A-load coordinates
    const int r0  = tid >> 2;           // 0..63
    const int r1  = r0 + 64;            // 64..127
    const int kq  = (tid & 3) * 4;      // 0,4,8,12
    const int arow0 = rowBase + r0;
    const int arow1 = rowBase + r1;
    const bool av0 = arow0 < NN;
    const bool av1 = arow1 < NN;
    const float inv0 = av0 ? g_inv[arow0] : 0.f;
    const float inv1 = av1 ? g_inv[arow1] : 0.f;

    // Fixed per-thread B-load coordinates
    const int bkr0 = tid >> 5;          // 0..7
    const int bkr1 = bkr0 + 8;          // 8..15
    const int bj   = (tid & 31) * 4;    // 0..124

    float acc[8][8];
    #pragma unroll
    for (int i = 0; i < 8; i++)
        #pragma unroll
        for (int j = 0; j < 8; j++) acc[i][j] = 0.f;

    for (int kb = 0; kb < 256; kb += 16) {
        // ---- load A tile (128 rows x 16 k), transpose into As[k][row] ----
        float4 a0 = make_float4(0.f, 0.f, 0.f, 0.f);
        float4 a1 = make_float4(0.f, 0.f, 0.f, 0.f);
        if (kb < 128) {
            int k = kb + kq;
            if (av0) {
                a0 = *reinterpret_cast<const float4*>(g_agg + (size_t)arow0 * DD + k);
                a0.x *= inv0; a0.y *= inv0; a0.z *= inv0; a0.w *= inv0;
            }
            if (av1) {
                a1 = *reinterpret_cast<const float4*>(g_agg + (size_t)arow1 * DD + k);
                a1.x *= inv1; a1.y *= inv1; a1.z *= inv1; a1.w *= inv1;
            }
        } else {
            int k = kb - 128 + kq;
            if (av0) a0 = *reinterpret_cast<const float4*>(h + (size_t)arow0 * DD + k);
            if (av1) a1 = *reinterpret_cast<const float4*>(h + (size_t)arow1 * DD + k);
        }
        As[(kq + 0) * ASTRIDE + r0] = a0.x;
        As[(kq + 1) * ASTRIDE + r0] = a0.y;
        As[(kq + 2) * ASTRIDE + r0] = a0.z;
        As[(kq + 3) * ASTRIDE + r0] = a0.w;
        As[(kq + 0) * ASTRIDE + r1] = a1.x;
        As[(kq + 1) * ASTRIDE + r1] = a1.y;
        As[(kq + 2) * ASTRIDE + r1] = a1.z;
        As[(kq + 3) * ASTRIDE + r1] = a1.w;

        // ---- load B tile (16 k x 128 cols) ----
        {
            int k0 = kb + bkr0;
            int k1 = kb + bkr1;
            const float* W0 = (k0 < 128) ? (Wl + (size_t)k0 * DD) : (Wr + (size_t)(k0 - 128) * DD);
            const float* W1 = (k1 < 128) ? (Wl + (size_t)k1 * DD) : (Wr + (size_t)(k1 - 128) * DD);
            *reinterpret_cast<float4*>(&Bs[bkr0 * 128 + bj]) =
                *reinterpret_cast<const float4*>(W0 + bj);
            *reinterpret_cast<float4*>(&Bs[bkr1 * 128 + bj]) =
                *reinterpret_cast<const float4*>(W1 + bj);
        }
        __syncthreads();

        // ---- compute ----
        #pragma unroll
        for (int kk = 0; kk < 16; kk++) {
            float a[8], b[8];
            *reinterpret_cast<float4*>(&a[0]) =
                *reinterpret_cast<const float4*>(&As[kk * ASTRIDE + ty * 8]);
            *reinterpret_cast<float4*>(&a[4]) =
                *reinterpret_cast<const float4*>(&As[kk * ASTRIDE + ty * 8 + 4]);
            *reinterpret_cast<float4*>(&b[0]) =
                *reinterpret_cast<const float4*>(&Bs[kk * 128 + tx * 8]);
            *reinterpret_cast<float4*>(&b[4]) =
                *reinterpret_cast<const float4*>(&Bs[kk * 128 + tx * 8 + 4]);
            #pragma unroll
            for (int i = 0; i < 8; i++)
                #pragma unroll
                for (int j = 0; j < 8; j++)
                    acc[i][j] += a[i] * b[j];
        }
        __syncthreads();
    }

    // ---- epilogue: + bias + residual (+ReLU) ----
    const int col = tx * 8;
    float4 bb0 = *reinterpret_cast<const float4*>(bias + col);
    float4 bb1 = *reinterpret_cast<const float4*>(bias + col + 4);
    #pragma unroll
    for (int i = 0; i < 8; i++) {
        int row = rowBase + ty * 8 + i;
        if (row < NN) {
            float4 hv0 = *reinterpret_cast<const float4*>(h + (size_t)row * DD + col);
            float4 hv1 = *reinterpret_cast<const float4*>(h + (size_t)row * DD + col + 4);
            float4 o0, o1;
            o0.x = acc[i][0] + bb0.x + hv0.x;
            o0.y = acc[i][1] + bb0.y + hv0.y;
            o0.z = acc[i][2] + bb0.z + hv0.z;
            o0.w = acc[i][3] + bb0.w + hv0.w;
            o1.x = acc[i][4] + bb1.x + hv1.x;
            o1.y = acc[i][5] + bb1.y + hv1.y;
            o1.z = acc[i][6] + bb1.z + hv1.z;
            o1.w = acc[i][7] + bb1.w + hv1.w;
            if (do_relu) {
                o0.x = fmaxf(o0.x, 0.f); o0.y = fmaxf(o0.y, 0.f);
                o0.z = fmaxf(o0.z, 0.f); o0.w = fmaxf(o0.w, 0.f);
                o1.x = fmaxf(o1.x, 0.f); o1.y = fmaxf(o1.y, 0.f);
                o1.z = fmaxf(o1.z, 0.f); o1.w = fmaxf(o1.w, 0.f);
            }
            *reinterpret_cast<float4*>(out + (size_t)row * DD + col) = o0;
            *reinterpret_cast<float4*>(out + (size_t)row * DD + col + 4) = o1;
        }
    }
}

// ---------------- launch ----------------
extern "C" void kernel_launch(void* const* d_in, const int* in_sizes, int n_in,
                              void* d_out, int out_size) {
    const float* x  = (const float*)d_in[0];
    const int*   ei = (const int*)d_in[1];
    const float* Wl = (const float*)d_in[2];
    const float* bl = (const float*)d_in[3];
    const float* Wr = (const float*)d_in[4];
    const int* src = ei;
    const int* dst = ei + NE;
    float* out = (float*)d_out;

    const int SB = 1184;              // 148 SMs * 8 blocks
    const int GB = (NN + 127) / 128;  // 782 gemm blocks

    // degree -> 1/max(cnt,1), once per launch (reused by all layers)
    zero_inv_kernel<<<(NN + 255) / 256, 256>>>();
    count_kernel<<<SB, 256>>>(dst);
    invert_kernel<<<(NN + 255) / 256, 256>>>();

    // layer 0: x -> g_buf0 (relu)
    zero_agg_kernel<<<SB, 256>>>();
    scatter_kernel<<<SB, 256>>>(x, src, dst, 0);
    sage_gemm_kernel<<<GB, 256>>>(x, out, Wl, Wr, bl, 0, 0, 1);

    // layer 1: g_buf0 -> g_buf1 (relu)
    zero_agg_kernel<<<SB, 256>>>();
    scatter_kernel<<<SB, 256>>>(x, src, dst, 1);
    sage_gemm_kernel<<<GB, 256>>>(x, out, Wl + DD * DD, Wr + DD * DD, bl + DD, 1, 1, 1);

    // layer 2: g_buf1 -> out (no relu)
    zero_agg_kernel<<<SB, 256>>>();
    scatter_kernel<<<SB, 256>>>(x, src, dst, 2);
    sage_gemm_kernel<<<GB, 256>>>(x, out, Wl + 2 * DD * DD, Wr + 2 * DD * DD, bl + 2 * DD, 2, 2, 0);
}

// round 4
// speedup vs baseline: 1.0044x; 1.0044x over previous
#include <cuda_runtime.h>
#include <cstdint>

#define NN 100000
#define NE 1600000
#define DD 128

// ---------------- static device scratch (no allocations allowed) ----------------
__device__ float g_agg[(size_t)NN * DD];   // scatter-sum accumulator
__device__ float g_buf0[(size_t)NN * DD];  // layer-1 output
__device__ float g_buf1[(size_t)NN * DD];  // layer-2 output
__device__ float g_inv[NN];                // degree count, then 1/max(cnt,1)

// ---------------- utility kernels ----------------
__global__ void zero_agg_kernel() {
    size_t stride = (size_t)gridDim.x * blockDim.x;
    size_t n4 = (size_t)NN * DD / 4;
    float4 z = make_float4(0.f, 0.f, 0.f, 0.f);
    for (size_t v = (size_t)blockIdx.x * blockDim.x + threadIdx.x; v < n4; v += stride)
        reinterpret_cast<float4*>(g_agg)[v] = z;
}

__global__ void zero_inv_kernel() {
    int i = blockIdx.x * blockDim.x + threadIdx.x;
    if (i < NN) g_inv[i] = 0.f;
}

__global__ void count_kernel(const int* __restrict__ dst) {
    int stride = gridDim.x * blockDim.x;
    for (int e = blockIdx.x * blockDim.x + threadIdx.x; e < NE; e += stride)
        atomicAdd(&g_inv[dst[e]], 1.0f);
}

__global__ void invert_kernel() {
    int i = blockIdx.x * blockDim.x + threadIdx.x;
    if (i < NN) g_inv[i] = 1.0f / fmaxf(g_inv[i], 1.0f);
}

// ---------------- scatter: one warp per edge, float4 atomicAdd intrinsic ------
// Each lane handles 16B: lane loads x[src][lane*4..lane*4+3] and issues one
// vector atomicAdd(float4) into agg[dst]. 32 lanes cover the full 512B row.
// hsel: 0 -> xin, 1 -> g_buf0, 2 -> g_buf1
__global__ void scatter_kernel(const float* __restrict__ xin,
                               const int* __restrict__ src,
                               const int* __restrict__ dst,
                               int hsel) {
    const float* __restrict__ x =
        (hsel == 0) ? xin : (hsel == 1) ? (const float*)g_buf0 : (const float*)g_buf1;
    int gw   = (blockIdx.x * blockDim.x + threadIdx.x) >> 5;
    int lane = threadIdx.x & 31;
    int nw   = (gridDim.x * blockDim.x) >> 5;
    for (int e = gw; e < NE; e += nw) {
        int s = __ldg(src + e);   // uniform within warp -> broadcast
        int d = __ldg(dst + e);
        float4 v = *reinterpret_cast<const float4*>(x + (size_t)s * DD + lane * 4);
        float4* p = reinterpret_cast<float4*>(g_agg + (size_t)d * DD + lane * 4);
        atomicAdd(p, v);   // native float4 atomicAdd (sm_90+), no inline PTX
    }
}

// ---------------- fused SGEMM: out = (agg*inv)@Wl + h@Wr + bl + h (+ReLU) -------
// Block tile 128x128, K=256 (concat [agg*inv | h] x [Wl;Wr]), BK=16,
// 256 threads, 8x8 micro-tile per thread.
#define ASTRIDE 132

__global__ __launch_bounds__(256, 2)
void sage_gemm_kernel(const float* __restrict__ xin,
                      float* __restrict__ oout,
                      const float* __restrict__ Wl,
                      const float* __restrict__ Wr,
                      const float* __restrict__ bias,
                      int hsel, int osel, int do_relu) {
    const float* __restrict__ h =
        (hsel == 0) ? xin : (hsel == 1) ? (const float*)g_buf0 : (const float*)g_buf1;
    float* __restrict__ out =
        (osel == 0) ? (float*)g_buf0 : (osel == 1) ? (float*)g_buf1 : oout;

    __shared__ float As[16 * ASTRIDE];  // [k][row], padded
    __shared__ float Bs[16 * 128];      // [k][col]

    const int tid = threadIdx.x;
    const int tx = tid & 15;            // col group
    const int ty = tid >> 4;            // row group
    const int rowBase = blockIdx.x * 128;

    // Fixed per-thread A-load coordinates
    const int r0  = tid >> 2;           // 0..63
    const int r1  = r0 + 64;            // 64..127
    const int kq  = (tid & 3) * 4;      // 0,4,8,12
    const int arow0 = rowBase + r0;
    const int arow1 = rowBase + r1;
    const bool av0 = arow0 < NN;
    const bool av1 = arow1 < NN;
    const float inv0 = av0 ? g_inv[arow0] : 0.f;
    const float inv1 = av1 ? g_inv[arow1] : 0.f;

    // Fixed per-thread B-load coordinates
    const int bkr0 = tid >> 5;          // 0..7
    const int bkr1 = bkr0 + 8;          // 8..15
    const int bj   = (tid & 31) * 4;    // 0..124

    float acc[8][8];
    #pragma unroll
    for (int i = 0; i < 8; i++)
        #pragma unroll
        for (int j = 0; j < 8; j++) acc[i][j] = 0.f;

    for (int kb = 0; kb < 256; kb += 16) {
        // ---- load A tile (128 rows x 16 k), transpose into As[k][row] ----
        float4 a0 = make_float4(0.f, 0.f, 0.f, 0.f);
        float4 a1 = make_float4(0.f, 0.f, 0.f, 0.f);
        if (kb < 128) {
            int k = kb + kq;
            if (av0) {
                a0 = *reinterpret_cast<const float4*>(g_agg + (size_t)arow0 * DD + k);
                a0.x *= inv0; a0.y *= inv0; a0.z *= inv0; a0.w *= inv0;
            }
            if (av1) {
                a1 = *reinterpret_cast<const float4*>(g_agg + (size_t)arow1 * DD + k);
                a1.x *= inv1; a1.y *= inv1; a1.z *= inv1; a1.w *= inv1;
            }
        } else {
            int k = kb - 128 + kq;
            if (av0) a0 = *reinterpret_cast<const float4*>(h + (size_t)arow0 * DD + k);
            if (av1) a1 = *reinterpret_cast<const float4*>(h + (size_t)arow1 * DD + k);
        }
        As[(kq + 0) * ASTRIDE + r0] = a0.x;
        As[(kq + 1) * ASTRIDE + r0] = a0.y;
        As[(kq + 2) * ASTRIDE + r0] = a0.z;
        As[(kq + 3) * ASTRIDE + r0] = a0.w;
        As[(kq + 0) * ASTRIDE + r1] = a1.x;
        As[(kq + 1) * ASTRIDE + r1] = a1.y;
        As[(kq + 2) * ASTRIDE + r1] = a1.z;
        As[(kq + 3) * ASTRIDE + r1] = a1.w;

        // ---- load B tile (16 k x 128 cols) ----
        {
            int k0 = kb + bkr0;
            int k1 = kb + bkr1;
            const float* W0 = (k0 < 128) ? (Wl + (size_t)k0 * DD) : (Wr + (size_t)(k0 - 128) * DD);
            const float* W1 = (k1 < 128) ? (Wl + (size_t)k1 * DD) : (Wr + (size_t)(k1 - 128) * DD);
            *reinterpret_cast<float4*>(&Bs[bkr0 * 128 + bj]) =
                *reinterpret_cast<const float4*>(W0 + bj);
            *reinterpret_cast<float4*>(&Bs[bkr1 * 128 + bj]) =
                *reinterpret_cast<const float4*>(W1 + bj);
        }
        __syncthreads();

        // ---- compute ----
        #pragma unroll
        for (int kk = 0; kk < 16; kk++) {
            float a[8], b[8];
            *reinterpret_cast<float4*>(&a[0]) =
                *reinterpret_cast<const float4*>(&As[kk * ASTRIDE + ty * 8]);
            *reinterpret_cast<float4*>(&a[4]) =
                *reinterpret_cast<const float4*>(&As[kk * ASTRIDE + ty * 8 + 4]);
            *reinterpret_cast<float4*>(&b[0]) =
                *reinterpret_cast<const float4*>(&Bs[kk * 128 + tx * 8]);
            *reinterpret_cast<float4*>(&b[4]) =
                *reinterpret_cast<const float4*>(&Bs[kk * 128 + tx * 8 + 4]);
            #pragma unroll
            for (int i = 0; i < 8; i++)
                #pragma unroll
                for (int j = 0; j < 8; j++)
                    acc[i][j] += a[i] * b[j];
        }
        __syncthreads();
    }

    // ---- epilogue: + bias + residual (+ReLU) ----
    const int col = tx * 8;
    float4 bb0 = *reinterpret_cast<const float4*>(bias + col);
    float4 bb1 = *reinterpret_cast<const float4*>(bias + col + 4);
    #pragma unroll
    for (int i = 0; i < 8; i++) {
        int row = rowBase + ty * 8 + i;
        if (row < NN) {
            float4 hv0 = *reinterpret_cast<const float4*>(h + (size_t)row * DD + col);
            float4 hv1 = *reinterpret_cast<const float4*>(h + (size_t)row * DD + col + 4);
            float4 o0, o1;
            o0.x = acc[i][0] + bb0.x + hv0.x;
            o0.y = acc[i][1] + bb0.y + hv0.y;
            o0.z = acc[i][2] + bb0.z + hv0.z;
            o0.w = acc[i][3] + bb0.w + hv0.w;
            o1.x = acc[i][4] + bb1.x + hv1.x;
            o1.y = acc[i][5] + bb1.y + hv1.y;
            o1.z = acc[i][6] + bb1.z + hv1.z;
            o1.w = acc[i][7] + bb1.w + hv1.w;
            if (do_relu) {
                o0.x = fmaxf(o0.x, 0.f); o0.y = fmaxf(o0.y, 0.f);
                o0.z = fmaxf(o0.z, 0.f); o0.w = fmaxf(o0.w, 0.f);
                o1.x = fmaxf(o1.x, 0.f); o1.y = fmaxf(o1.y, 0.f);
                o1.z = fmaxf(o1.z, 0.f); o1.w = fmaxf(o1.w, 0.f);
            }
            *reinterpret_cast<float4*>(out + (size_t)row * DD + col) = o0;
            *reinterpret_cast<float4*>(out + (size_t)row * DD + col + 4) = o1;
        }
    }
}

// ---------------- launch ----------------
extern "C" void kernel_launch(void* const* d_in, const int* in_sizes, int n_in,
                              void* d_out, int out_size) {
    const float* x  = (const float*)d_in[0];
    const int*   ei = (const int*)d_in[1];
    const float* Wl = (const float*)d_in[2];
    const float* bl = (const float*)d_in[3];
    const float* Wr = (const float*)d_in[4];
    const int* src = ei;
    const int* dst = ei + NE;
    float* out = (float*)d_out;

    const int SB = 1184;              // 148 SMs * 8 blocks
    const int GB = (NN + 127) / 128;  // 782 gemm blocks

    // degree -> 1/max(cnt,1), once per launch (reused by all layers)
    zero_inv_kernel<<<(NN + 255) / 256, 256>>>();
    count_kernel<<<SB, 256>>>(dst);
    invert_kernel<<<(NN + 255) / 256, 256>>>();

    // layer 0: x -> g_buf0 (relu)
    zero_agg_kernel<<<SB, 256>>>();
    scatter_kernel<<<SB, 256>>>(x, src, dst, 0);
    sage_gemm_kernel<<<GB, 256>>>(x, out, Wl, Wr, bl, 0, 0, 1);

    // layer 1: g_buf0 -> g_buf1 (relu)
    zero_agg_kernel<<<SB, 256>>>();
    scatter_kernel<<<SB, 256>>>(x, src, dst, 1);
    sage_gemm_kernel<<<GB, 256>>>(x, out, Wl + DD * DD, Wr + DD * DD, bl + DD, 1, 1, 1);

    // layer 2: g_buf1 -> out (no relu)
    zero_agg_kernel<<<SB, 256>>>();
    scatter_kernel<<<SB, 256>>>(x, src, dst, 2);
    sage_gemm_kernel<<<GB, 256>>>(x, out, Wl + 2 * DD * DD, Wr + 2 * DD * DD, bl + 2 * DD, 2, 2, 0);
}